// round 2
// baseline (speedup 1.0000x reference)
#include <cuda_runtime.h>
#include <stdint.h>

// Problem collapse: the GNN stack output is discarded by the reference.
// Effective computation:
//   z   = x[samples[:,0]] * x[samples[:,1]]          [S, 256]
//   z   = relu(z @ lin1_W + lin1_b)                  [S, 256]
//   out = z @ lin2_W + lin2_b                        [S, 2]
// Fused into one gather-product SGEMM (M=S, N=256, K=256) with a warp-reduced
// N=2 epilogue GEMM.

#define BM 32
#define BN 256
#define BK 16
#define KD 256   // D_IN == D_HID == 256

__global__ __launch_bounds__(256) void fused_pair_mlp(
    const float* __restrict__ x,          // [n_nodes, 256]
    const void*  __restrict__ samples_raw,// [S, 2] int64 OR int32 (detected)
    const float* __restrict__ W1,         // [256, 256] (lin1_W)
    const float* __restrict__ b1,         // [256]      (lin1_b)
    const float* __restrict__ W2,         // [256, 2]   (lin2_W)
    const float* __restrict__ b2,         // [2]        (lin2_b)
    float* __restrict__ out,              // [S, 2]
    int S, int n_nodes)
{
    // A tile padded to 36-float stride: keeps float4 rows 16B-aligned and
    // reduces the gather-store STS conflict to 2-way.
    __shared__ __align__(16) float As[BK][36];
    __shared__ __align__(16) float Bs[BK][BN];

    const int tid = threadIdx.x;
    const int m0  = blockIdx.x * BM;

    // ---- dtype detection: int64 vs int32 sample indices (uniform across grid)
    const long long* s64 = (const long long*)samples_raw;
    const int*       s32 = (const int*)samples_raw;
    bool is64 = true;
    #pragma unroll
    for (int i = 0; i < 4; ++i) {
        long long v = __ldg(&s64[i]);
        if (v < 0 || v >= (long long)n_nodes) is64 = false;
    }

    // ---- gather-load mapping: lanes 0..15 cover 16 consecutive k of one row
    const int km = tid & (BK - 1);   // k within tile, 0..15
    const int mr = tid >> 4;         // sample-row 0..15; also handles mr+16

    int r0 = m0 + mr;       if (r0 >= S) r0 = 0;
    int r1 = m0 + mr + 16;  if (r1 >= S) r1 = 0;

    long long ia0, ib0, ia1, ib1;
    if (is64) {
        ia0 = s64[(long long)r0 * 2];     ib0 = s64[(long long)r0 * 2 + 1];
        ia1 = s64[(long long)r1 * 2];     ib1 = s64[(long long)r1 * 2 + 1];
    } else {
        ia0 = s32[r0 * 2];                ib0 = s32[r0 * 2 + 1];
        ia1 = s32[r1 * 2];                ib1 = s32[r1 * 2 + 1];
    }
    const float* xa0 = x + ia0 * KD + km;
    const float* xb0 = x + ib0 * KD + km;
    const float* xa1 = x + ia1 * KD + km;
    const float* xb1 = x + ib1 * KD + km;

    // ---- compute mapping: warp ty handles rows ty*4..ty*4+3, lane tx cols tx*8..tx*8+7
    const int ty = tid >> 5;
    const int tx = tid & 31;

    float acc[4][8];
    #pragma unroll
    for (int r = 0; r < 4; ++r)
        #pragma unroll
        for (int c = 0; c < 8; ++c) acc[r][c] = 0.f;

    // ---- B-tile load map: 4x float4 per thread, fully coalesced
    const int brow = tid >> 6;          // 0..3, +4*i
    const int bcol = (tid & 63) * 4;    // float4 column

    #pragma unroll 1
    for (int kt = 0; kt < KD / BK; ++kt) {
        const int k0 = kt * BK;

        // global loads first (overlap with previous-tile drain)
        const float p0 = xa0[k0] * xb0[k0];
        const float p1 = xa1[k0] * xb1[k0];
        float4 bv[4];
        #pragma unroll
        for (int i = 0; i < 4; ++i)
            bv[i] = *(const float4*)&W1[(size_t)(k0 + brow + i * 4) * BN + bcol];

        __syncthreads();
        As[km][mr]      = p0;
        As[km][mr + 16] = p1;
        #pragma unroll
        for (int i = 0; i < 4; ++i)
            *(float4*)&Bs[brow + i * 4][bcol] = bv[i];
        __syncthreads();

        #pragma unroll
        for (int k = 0; k < BK; ++k) {
            const float4 av  = *(const float4*)&As[k][ty * 4];
            const float4 b0v = *(const float4*)&Bs[k][tx * 8];
            const float4 b1v = *(const float4*)&Bs[k][tx * 8 + 4];
            const float a[4]  = {av.x, av.y, av.z, av.w};
            const float bb[8] = {b0v.x, b0v.y, b0v.z, b0v.w,
                                 b1v.x, b1v.y, b1v.z, b1v.w};
            #pragma unroll
            for (int r = 0; r < 4; ++r)
                #pragma unroll
                for (int c = 0; c < 8; ++c)
                    acc[r][c] = fmaf(a[r], bb[c], acc[r][c]);
        }
    }

    // ---- epilogue: bias + relu + [256,2] GEMM, warp-reduced over columns
    float bias[8], w0c[8], w1c[8];
    #pragma unroll
    for (int c = 0; c < 8; ++c) {
        const int col = tx * 8 + c;
        bias[c] = b1[col];
        const float2 w = *(const float2*)&W2[col * 2];
        w0c[c] = w.x; w1c[c] = w.y;
    }
    const float ob0 = b2[0], ob1 = b2[1];

    #pragma unroll
    for (int r = 0; r < 4; ++r) {
        float o0 = 0.f, o1 = 0.f;
        #pragma unroll
        for (int c = 0; c < 8; ++c) {
            const float z = fmaxf(acc[r][c] + bias[c], 0.f);
            o0 = fmaf(z, w0c[c], o0);
            o1 = fmaf(z, w1c[c], o1);
        }
        #pragma unroll
        for (int off = 16; off > 0; off >>= 1) {
            o0 += __shfl_xor_sync(0xffffffffu, o0, off);
            o1 += __shfl_xor_sync(0xffffffffu, o1, off);
        }
        const int srow = m0 + ty * 4 + r;
        if (tx == 0 && srow < S) {
            out[srow * 2 + 0] = o0 + ob0;
            out[srow * 2 + 1] = o1 + ob1;
        }
    }
}

extern "C" void kernel_launch(void* const* d_in, const int* in_sizes, int n_in,
                              void* d_out, int out_size) {
    // metadata order: x_feature, edge_index, samples, W1, b1, W2, b2,
    //                 lin1_W, lin1_b, lin2_W, lin2_b
    const float* x       = (const float*)d_in[0];
    const void*  samples = d_in[2];
    const float* lin1_W  = (const float*)d_in[7];
    const float* lin1_b  = (const float*)d_in[8];
    const float* lin2_W  = (const float*)d_in[9];
    const float* lin2_b  = (const float*)d_in[10];
    float* out = (float*)d_out;

    const int S       = in_sizes[2] / 2;    // samples is [S,2]
    const int n_nodes = in_sizes[0] / KD;   // x_feature is [n_nodes, 256]
    const int grid    = (S + BM - 1) / BM;

    fused_pair_mlp<<<grid, 256>>>(x, samples, lin1_W, lin1_b, lin2_W, lin2_b,
                                  out, S, n_nodes);
}

// round 3
// speedup vs baseline: 1.3556x; 1.3556x over previous
#include <cuda_runtime.h>
#include <stdint.h>

// Effective computation (GNN stack is dead code in the reference):
//   z   = x[samples[:,0]] * x[samples[:,1]]          [S, 256]
//   z   = relu(z @ lin1_W + lin1_b)                  [S, 256]
//   out = z @ lin2_W + lin2_b                        [S, 2]
//
// R2: 64x256x8 double-buffered SGEMM, 8x8 microtile, 2D warp-lane layout
// (4 row-groups x 8 col-groups) to slash smem crossbar traffic per FMA.

#define BM 64
#define BN 256
#define BK 8
#define KD 256
#define ASTR 68   // BM + 4 pad: conflict-free gather STS + aligned LDS.128

__global__ __launch_bounds__(256, 2) void fused_pair_mlp(
    const float* __restrict__ x,           // [n_nodes, 256]
    const void*  __restrict__ samples_raw, // [S,2] int64 OR int32 (detected)
    const float* __restrict__ W1,          // [256, 256] lin1_W
    const float* __restrict__ b1,          // [256]      lin1_b
    const float* __restrict__ W2,          // [256, 2]   lin2_W
    const float* __restrict__ b2,          // [2]        lin2_b
    float* __restrict__ out,               // [S, 2]
    int S, int n_nodes)
{
    __shared__ __align__(16) float As[2][BK][ASTR];
    __shared__ __align__(16) float Bs[2][BK][BN];
    __shared__ float2 red[BM][4];

    const int tid = threadIdx.x;
    const int m0  = blockIdx.x * BM;

    // ---- dtype detection: int64 vs int32 sample indices (uniform everywhere)
    const long long* s64 = (const long long*)samples_raw;
    const int*       s32 = (const int*)samples_raw;
    bool is64 = true;
    #pragma unroll
    for (int i = 0; i < 4; ++i) {
        long long v = __ldg(&s64[i]);
        if (v < 0 || v >= (long long)n_nodes) is64 = false;
    }

    // ---- A staging map: thread t -> (row = t>>2, k-pair = (t&3)*2)
    const int arow = tid >> 2;
    const int kq   = (tid & 3) * 2;
    int gr = m0 + arow; if (gr >= S) gr = S - 1;
    long long ia, ib;
    if (is64) { ia = s64[(long long)gr * 2]; ib = s64[(long long)gr * 2 + 1]; }
    else      { ia = s32[gr * 2];            ib = s32[gr * 2 + 1]; }
    const float* pa = x + ia * KD + kq;
    const float* pb = x + ib * KD + kq;

    // ---- B staging map: thread t -> (kk = t>>5, n = (t&31)*4 and +128)
    const int bk = tid >> 5;
    const int bn = (tid & 31) * 4;
    const float* pw = W1 + (size_t)bk * BN + bn;

    // ---- compute map: 8 warps as 2x4; lanes as 4 row-groups x 8 col-groups
    const int lane = tid & 31;
    const int w    = tid >> 5;
    const int wr   = w >> 2;                 // 0..1
    const int wc   = w & 3;                  // 0..3
    const int rg   = wr * 4 + (lane >> 3);   // 0..7  -> rows rg*8 .. rg*8+7
    const int cg   = wc * 8 + (lane & 7);    // 0..31 -> cols cg*8 .. cg*8+7
    const int cgrp = lane & 7;               // col-group lane within 8

    float acc[8][8];
    #pragma unroll
    for (int r = 0; r < 8; ++r)
        #pragma unroll
        for (int c = 0; c < 8; ++c) acc[r][c] = 0.f;

    // ---- prologue: stage k-tile 0 into buffer 0
    {
        const float2 a2 = *(const float2*)pa;
        const float2 b2v = *(const float2*)pb;
        As[0][kq][arow]     = a2.x * b2v.x;
        As[0][kq + 1][arow] = a2.y * b2v.y;
        const float4 w0 = *(const float4*)pw;
        const float4 w1 = *(const float4*)(pw + 128);
        *(float4*)&Bs[0][bk][bn]       = w0;
        *(float4*)&Bs[0][bk][bn + 128] = w1;
    }
    __syncthreads();

    // ---- main loop over 32 k-tiles, double-buffered
    #pragma unroll 1
    for (int kt = 0; kt < KD / BK; ++kt) {
        const int cur = kt & 1;
        const int nxt = cur ^ 1;

        // issue next tile's global loads early (overlap with compute)
        float2 a2, b2v; float4 w0, w1;
        const bool more = (kt + 1 < KD / BK);
        if (more) {
            const int k0n = (kt + 1) * BK;
            a2  = *(const float2*)(pa + k0n);
            b2v = *(const float2*)(pb + k0n);
            w0  = *(const float4*)(pw + (size_t)k0n * BN);
            w1  = *(const float4*)(pw + (size_t)k0n * BN + 128);
        }

        // compute on current buffer
        #pragma unroll
        for (int k = 0; k < BK; ++k) {
            float a[8], bb[8];
            const float4 av0 = *(const float4*)&As[cur][k][rg * 8];
            const float4 av1 = *(const float4*)&As[cur][k][rg * 8 + 4];
            const float4 bv0 = *(const float4*)&Bs[cur][k][cg * 8];
            const float4 bv1 = *(const float4*)&Bs[cur][k][cg * 8 + 4];
            a[0]=av0.x; a[1]=av0.y; a[2]=av0.z; a[3]=av0.w;
            a[4]=av1.x; a[5]=av1.y; a[6]=av1.z; a[7]=av1.w;
            bb[0]=bv0.x; bb[1]=bv0.y; bb[2]=bv0.z; bb[3]=bv0.w;
            bb[4]=bv1.x; bb[5]=bv1.y; bb[6]=bv1.z; bb[7]=bv1.w;
            #pragma unroll
            for (int r = 0; r < 8; ++r)
                #pragma unroll
                for (int c = 0; c < 8; ++c)
                    acc[r][c] = fmaf(a[r], bb[c], acc[r][c]);
        }

        if (more) {
            As[nxt][kq][arow]     = a2.x * b2v.x;
            As[nxt][kq + 1][arow] = a2.y * b2v.y;
            *(float4*)&Bs[nxt][bk][bn]       = w0;
            *(float4*)&Bs[nxt][bk][bn + 128] = w1;
            __syncthreads();
        }
    }

    // ---- epilogue: bias + relu + [256,2] GEMM
    float bias[8], w0c[8], w1c[8];
    #pragma unroll
    for (int c = 0; c < 8; ++c) {
        const int col = cg * 8 + c;
        bias[c] = b1[col];
        const float2 ww = *(const float2*)&W2[col * 2];
        w0c[c] = ww.x; w1c[c] = ww.y;
    }

    float o0[8], o1[8];
    #pragma unroll
    for (int r = 0; r < 8; ++r) {
        float s0 = 0.f, s1 = 0.f;
        #pragma unroll
        for (int c = 0; c < 8; ++c) {
            const float z = fmaxf(acc[r][c] + bias[c], 0.f);
            s0 = fmaf(z, w0c[c], s0);
            s1 = fmaf(z, w1c[c], s1);
        }
        // reduce over the 8 col-group lanes (same rows, masks 1,2,4)
        #pragma unroll
        for (int off = 1; off < 8; off <<= 1) {
            s0 += __shfl_xor_sync(0xffffffffu, s0, off);
            s1 += __shfl_xor_sync(0xffffffffu, s1, off);
        }
        o0[r] = s0; o1[r] = s1;
    }

    __syncthreads();   // As/Bs done; red[] writes ordered vs readers below
    if (cgrp == 0) {
        #pragma unroll
        for (int r = 0; r < 8; ++r)
            red[rg * 8 + r][wc] = make_float2(o0[r], o1[r]);
    }
    __syncthreads();

    if (tid < BM) {
        const int srow = m0 + tid;
        if (srow < S) {
            float2 s = red[tid][0];
            #pragma unroll
            for (int q = 1; q < 4; ++q) {
                s.x += red[tid][q].x;
                s.y += red[tid][q].y;
            }
            out[srow * 2 + 0] = s.x + b2[0];
            out[srow * 2 + 1] = s.y + b2[1];
        }
    }
}

extern "C" void kernel_launch(void* const* d_in, const int* in_sizes, int n_in,
                              void* d_out, int out_size) {
    // metadata order: x_feature, edge_index, samples, W1, b1, W2, b2,
    //                 lin1_W, lin1_b, lin2_W, lin2_b
    const float* x       = (const float*)d_in[0];
    const void*  samples = d_in[2];
    const float* lin1_W  = (const float*)d_in[7];
    const float* lin1_b  = (const float*)d_in[8];
    const float* lin2_W  = (const float*)d_in[9];
    const float* lin2_b  = (const float*)d_in[10];
    float* out = (float*)d_out;

    const int S       = in_sizes[2] / 2;
    const int n_nodes = in_sizes[0] / KD;
    const int grid    = (S + BM - 1) / BM;

    fused_pair_mlp<<<grid, 256>>>(x, samples, lin1_W, lin1_b, lin2_W, lin2_b,
                                  out, S, n_nodes);
}

// round 5
// speedup vs baseline: 3.2725x; 2.4140x over previous
#include <cuda_runtime.h>
#include <cuda_bf16.h>
#include <stdint.h>

// Effective computation (GNN stack is dead code in the reference):
//   z   = x[samples[:,0]] * x[samples[:,1]]          [S, 256]
//   z   = relu(z @ lin1_W + lin1_b)                  [S, 256]
//   out = z @ lin2_W + lin2_b                        [S, 2]
//
// R4: tcgen05 unavailable (harness targets plain sm_100, no 'a' features).
// Use family-stable mma.sync bf16 (m16n8k16) with 2-term bf16 split:
//   z@W ~= zh@Wh + zh@Wl + zl@Wh   (error ~2^-16, well under 1e-3)
// CTA 64x256xK256, 8 warps (2x4), warp tile 32x64, K-chunks of 32.

#define KD  256
#define BM  64
#define KC  32
#define NCH 8

// dynamic smem byte offsets (rows padded to 40 bf16 = 80B, conflict-free)
#define AH_OFF  0        // 64*80   = 5120
#define AL_OFF  5120
#define BH_OFF  10240    // 256*80  = 20480
#define BL_OFF  30720
#define SB1_OFF 51200    // 256 f32
#define SW2_OFF 52224    // 256 float2
#define RED_OFF 54272    // 64*4 float2
#define DSMEM   56320

__device__ __nv_bfloat16 g_Wh[KD * KD];   // chunk-major: [c][n][32]
__device__ __nv_bfloat16 g_Wl[KD * KD];

__global__ void conv_w_kernel(const float* __restrict__ W1) {
    const int idx = blockIdx.x * 256 + threadIdx.x;   // 65536 total
    const int n = idx & 255;          // coalesced read of W1[k][n]
    const int k = idx >> 8;
    const float w = W1[(size_t)k * KD + n];
    const __nv_bfloat16 h = __float2bfloat16(w);
    const __nv_bfloat16 l = __float2bfloat16(w - __bfloat162float(h));
    const int dst = (k >> 5) * (KD * KC) + n * KC + (k & 31);
    g_Wh[dst] = h;
    g_Wl[dst] = l;
}

__device__ __forceinline__ uint32_t smem_u32(const void* p) {
    uint32_t a;
    asm("{ .reg .u64 t; cvta.to.shared.u64 t, %1; cvt.u32.u64 %0, t; }"
        : "=r"(a) : "l"(p));
    return a;
}
__device__ __forceinline__ uint32_t pack_bf16x2(float lo, float hi) {
    uint32_t r;   // low 16 bits <- lo
    asm("cvt.rn.bf16x2.f32 %0, %1, %2;" : "=r"(r) : "f"(hi), "f"(lo));
    return r;
}
__device__ __forceinline__ void split8(const float* z, uint4& h, uint4& l) {
    uint32_t hw[4], lw[4];
#pragma unroll
    for (int q = 0; q < 4; ++q) {
        const float z0 = z[2 * q], z1 = z[2 * q + 1];
        const uint32_t hv = pack_bf16x2(z0, z1);
        const float h0 = __uint_as_float(hv << 16);
        const float h1 = __uint_as_float(hv & 0xffff0000u);
        hw[q] = hv;
        lw[q] = pack_bf16x2(z0 - h0, z1 - h1);
    }
    h = make_uint4(hw[0], hw[1], hw[2], hw[3]);
    l = make_uint4(lw[0], lw[1], lw[2], lw[3]);
}

#define LDSM4(r, addr) \
    asm volatile("ldmatrix.sync.aligned.m8n8.x4.shared.b16 {%0,%1,%2,%3}, [%4];" \
        : "=r"((r)[0]), "=r"((r)[1]), "=r"((r)[2]), "=r"((r)[3]) : "r"(addr))

#define MMA_BF16(c, a, b0, b1) \
    asm volatile("mma.sync.aligned.m16n8k16.row.col.f32.bf16.bf16.f32 " \
        "{%0,%1,%2,%3}, {%4,%5,%6,%7}, {%8,%9}, {%0,%1,%2,%3};" \
        : "+f"((c)[0]), "+f"((c)[1]), "+f"((c)[2]), "+f"((c)[3]) \
        : "r"((a)[0]), "r"((a)[1]), "r"((a)[2]), "r"((a)[3]), "r"(b0), "r"(b1))

__global__ __launch_bounds__(256, 2) void fused_pair_mlp_mma(
    const float* __restrict__ x,
    const void*  __restrict__ samples_raw,
    const float* __restrict__ b1,
    const float* __restrict__ W2,
    const float* __restrict__ b2,
    float* __restrict__ out,
    int S, int n_nodes)
{
    extern __shared__ __align__(16) char dsm[];
    const uint32_t sb = smem_u32(dsm);

    const int tid  = threadIdx.x;
    const int lane = tid & 31;
    const int wid  = tid >> 5;
    const int mw   = wid >> 2;      // 0..1  (M 2x32)
    const int nw   = wid & 3;       // 0..3  (N 4x64)
    const int m0   = blockIdx.x * BM;

    // stage bias/W2 into smem
    {
        float* sb1f  = (float*)(dsm + SB1_OFF);
        float2* sw2f = (float2*)(dsm + SW2_OFF);
        sb1f[tid] = b1[tid];
        sw2f[tid] = *(const float2*)&W2[tid * 2];
    }

    // ---- dtype detection: int64 vs int32 sample indices (uniform)
    const long long* s64 = (const long long*)samples_raw;
    const int*       s32 = (const int*)samples_raw;
    bool is64 = true;
#pragma unroll
    for (int i = 0; i < 4; ++i) {
        long long v = __ldg(&s64[i]);
        if (v < 0 || v >= (long long)n_nodes) is64 = false;
    }

    // ---- A staging map: thread t -> row t>>2 (0..63), 8 k's at (t&3)*8
    const int arow = tid >> 2;
    const int kg   = (tid & 3) * 8;
    int gr = m0 + arow; if (gr >= S) gr = S - 1;
    long long ia, ib;
    if (is64) { ia = s64[(long long)gr * 2]; ib = s64[(long long)gr * 2 + 1]; }
    else      { ia = s32[gr * 2];            ib = s32[gr * 2 + 1]; }
    const float* xa = x + ia * KD + kg;
    const float* xb = x + ib * KD + kg;

    // ---- ldmatrix per-lane base addresses
    // A (16x16 tiles, row-major, stride 40 elems)
    const uint32_t aBaseH = sb + AH_OFF +
        2u * ((mw * 32 + (lane & 15)) * 40 + ((lane >> 4) << 3));
    const uint32_t aBaseL = aBaseH + (AL_OFF - AH_OFF);
    // B ([n][k] storage, n8xk16 tile pairs)
    const uint32_t bBaseH = sb + BH_OFF +
        2u * ((nw * 64 + ((lane >> 4) << 3) + (lane & 7)) * 40 +
              (((lane >> 3) & 1) << 3));
    const uint32_t bBaseL = bBaseH + (BL_OFF - BH_OFF);

    float acc[2][8][4];
#pragma unroll
    for (int i = 0; i < 2; ++i)
#pragma unroll
        for (int j = 0; j < 8; ++j)
#pragma unroll
            for (int q = 0; q < 4; ++q) acc[i][j][q] = 0.f;

    // ---- K loop: 8 chunks of 32
#pragma unroll 1
    for (int c = 0; c < NCH; ++c) {
        const int k0 = c * KC;

        // global loads (overlap previous chunk's MMA before the sync)
        const float4 va0 = *(const float4*)(xa + k0);
        const float4 va1 = *(const float4*)(xa + k0 + 4);
        const float4 vb0 = *(const float4*)(xb + k0);
        const float4 vb1 = *(const float4*)(xb + k0 + 4);
        const uint4* gh = (const uint4*)(g_Wh + (size_t)c * (KD * KC) + tid * KC);
        const uint4* gl = (const uint4*)(g_Wl + (size_t)c * (KD * KC) + tid * KC);
        uint4 wh[4], wl[4];
#pragma unroll
        for (int j = 0; j < 4; ++j) { wh[j] = gh[j]; wl[j] = gl[j]; }

        __syncthreads();   // previous chunk's consumers done

        // A: product + split + store
        {
            float z[8];
            z[0]=va0.x*vb0.x; z[1]=va0.y*vb0.y; z[2]=va0.z*vb0.z; z[3]=va0.w*vb0.w;
            z[4]=va1.x*vb1.x; z[5]=va1.y*vb1.y; z[6]=va1.z*vb1.z; z[7]=va1.w*vb1.w;
            uint4 h, l;
            split8(z, h, l);
            *(uint4*)(dsm + AH_OFF + arow * 80 + (tid & 3) * 16) = h;
            *(uint4*)(dsm + AL_OFF + arow * 80 + (tid & 3) * 16) = l;
        }
        // B: copy preconverted chunk (row n = tid)
        {
            char* bh = dsm + BH_OFF + tid * 80;
            char* bl = dsm + BL_OFF + tid * 80;
#pragma unroll
            for (int j = 0; j < 4; ++j) {
                ((uint4*)bh)[j] = wh[j];
                ((uint4*)bl)[j] = wl[j];
            }
        }
        __syncthreads();

        // compute: 2 k16 steps x (2 m-tiles x 8 n-tiles) x 3 split terms
#pragma unroll
        for (int kk = 0; kk < 2; ++kk) {
            uint32_t ah[2][4], al[2][4];
            LDSM4(ah[0], aBaseH + kk * 32);
            LDSM4(ah[1], aBaseH + 1280 + kk * 32);
            LDSM4(al[0], aBaseL + kk * 32);
            LDSM4(al[1], aBaseL + 1280 + kk * 32);
#pragma unroll
            for (int pr = 0; pr < 4; ++pr) {
                uint32_t bh[4], blr[4];
                LDSM4(bh,  bBaseH + pr * 1280 + kk * 32);
                LDSM4(blr, bBaseL + pr * 1280 + kk * 32);
#pragma unroll
                for (int tm = 0; tm < 2; ++tm) {
                    MMA_BF16(acc[tm][2 * pr],     ah[tm], bh[0],  bh[1]);
                    MMA_BF16(acc[tm][2 * pr],     ah[tm], blr[0], blr[1]);
                    MMA_BF16(acc[tm][2 * pr],     al[tm], bh[0],  bh[1]);
                    MMA_BF16(acc[tm][2 * pr + 1], ah[tm], bh[2],  bh[3]);
                    MMA_BF16(acc[tm][2 * pr + 1], ah[tm], blr[2], blr[3]);
                    MMA_BF16(acc[tm][2 * pr + 1], al[tm], bh[2],  bh[3]);
                }
            }
        }
    }

    // ---- epilogue: bias + relu + [256,2] GEMM, reduce in-warp then smem
    const float*  sb1f = (const float*)(dsm + SB1_OFF);
    const float2* sw2f = (const float2*)(dsm + SW2_OFF);
    float2* red = (float2*)(dsm + RED_OFF);   // [64][4]

    const int lr = lane >> 2;
    const int lc = (lane & 3) * 2;
#pragma unroll
    for (int tm = 0; tm < 2; ++tm) {
#pragma unroll
        for (int hh = 0; hh < 2; ++hh) {
            const int row = mw * 32 + tm * 16 + lr + hh * 8;
            float o0 = 0.f, o1 = 0.f;
#pragma unroll
            for (int tn = 0; tn < 8; ++tn) {
                const int cb = nw * 64 + tn * 8 + lc;
                const float z0 = fmaxf(acc[tm][tn][hh * 2 + 0] + sb1f[cb], 0.f);
                const float z1 = fmaxf(acc[tm][tn][hh * 2 + 1] + sb1f[cb + 1], 0.f);
                const float2 w0 = sw2f[cb];
                const float2 w1 = sw2f[cb + 1];
                o0 = fmaf(z0, w0.x, fmaf(z1, w1.x, o0));
                o1 = fmaf(z0, w0.y, fmaf(z1, w1.y, o1));
            }
            o0 += __shfl_xor_sync(0xffffffffu, o0, 1);
            o0 += __shfl_xor_sync(0xffffffffu, o0, 2);
            o1 += __shfl_xor_sync(0xffffffffu, o1, 1);
            o1 += __shfl_xor_sync(0xffffffffu, o1, 2);
            if ((lane & 3) == 0) red[row * 4 + nw] = make_float2(o0, o1);
        }
    }
    __syncthreads();

    if (tid < BM) {
        const int m = m0 + tid;
        if (m < S) {
            float2 s = red[tid * 4];
#pragma unroll
            for (int q = 1; q < 4; ++q) {
                s.x += red[tid * 4 + q].x;
                s.y += red[tid * 4 + q].y;
            }
            float2 o;
            o.x = s.x + b2[0];
            o.y = s.y + b2[1];
            *(float2*)(out + m * 2) = o;
        }
    }
}

extern "C" void kernel_launch(void* const* d_in, const int* in_sizes, int n_in,
                              void* d_out, int out_size) {
    // metadata order: x_feature, edge_index, samples, W1, b1, W2, b2,
    //                 lin1_W, lin1_b, lin2_W, lin2_b
    const float* x       = (const float*)d_in[0];
    const void*  samples = d_in[2];
    const float* lin1_W  = (const float*)d_in[7];
    const float* lin1_b  = (const float*)d_in[8];
    const float* lin2_W  = (const float*)d_in[9];
    const float* lin2_b  = (const float*)d_in[10];
    float* out = (float*)d_out;

    const int S       = in_sizes[2] / 2;
    const int n_nodes = in_sizes[0] / KD;
    const int grid    = (S + BM - 1) / BM;

    conv_w_kernel<<<256, 256>>>(lin1_W);

    cudaFuncSetAttribute(fused_pair_mlp_mma,
                         cudaFuncAttributeMaxDynamicSharedMemorySize, DSMEM);
    fused_pair_mlp_mma<<<grid, 256, DSMEM>>>(
        x, samples, lin1_b, lin2_W, lin2_b, out, S, n_nodes);
}

// round 6
// speedup vs baseline: 4.0338x; 1.2326x over previous
#include <cuda_runtime.h>
#include <cuda_bf16.h>
#include <stdint.h>

// Effective computation (GNN stack is dead code in the reference):
//   z   = x[samples[:,0]] * x[samples[:,1]]          [S, 256]
//   z   = relu(z @ lin1_W + lin1_b)                  [S, 256]
//   out = z @ lin2_W + lin2_b                        [S, 2]
//
// R5: mma.sync bf16 (m16n8k16) 2-term split, B operand pre-packed in exact
// fragment layout (one LDG.128 per n8-tile, no B smem round-trip),
// warp tile 64x64, CTA 128x256, double-buffered A smem.

#define KD  256
#define BM  128
#define KC  32
#define NCH 8

#define ABUF  20480              // per-buffer bytes: AH 10240 + AL 10240
#define DSMEM (2 * ABUF)         // 40960

// W1 fragments: [c][kk][ntile][lane] -> uint4 {b0h, b1h, b0l, b1l}
__device__ uint4 g_Wf[NCH * 2 * 32 * 32];

__device__ __forceinline__ uint32_t pack_bf16x2(float lo, float hi) {
    uint32_t r;   // low 16 <- lo
    asm("cvt.rn.bf16x2.f32 %0, %1, %2;" : "=r"(r) : "f"(hi), "f"(lo));
    return r;
}
__device__ __forceinline__ void split2(float a, float b, uint32_t& h, uint32_t& l) {
    h = pack_bf16x2(a, b);
    const float ha = __uint_as_float(h << 16);
    const float hb = __uint_as_float(h & 0xffff0000u);
    l = pack_bf16x2(a - ha, b - hb);
}

__global__ void conv_w_kernel(const float* __restrict__ W1) {
    const int idx  = blockIdx.x * 256 + threadIdx.x;   // 16384 total
    const int lane = idx & 31;
    const int tile = (idx >> 5) & 31;
    const int kk   = (idx >> 10) & 1;
    const int c    = idx >> 11;
    const int n  = tile * 8 + (lane >> 2);
    const int k0 = c * KC + kk * 16 + (lane & 3) * 2;
    const float w00 = W1[(size_t)k0 * KD + n];
    const float w01 = W1[(size_t)(k0 + 1) * KD + n];
    const float w10 = W1[(size_t)(k0 + 8) * KD + n];
    const float w11 = W1[(size_t)(k0 + 9) * KD + n];
    uint32_t h0, l0, h1, l1;
    split2(w00, w01, h0, l0);
    split2(w10, w11, h1, l1);
    g_Wf[idx] = make_uint4(h0, h1, l0, l1);
}

__device__ __forceinline__ uint32_t smem_u32(const void* p) {
    uint32_t a;
    asm("{ .reg .u64 t; cvta.to.shared.u64 t, %1; cvt.u32.u64 %0, t; }"
        : "=r"(a) : "l"(p));
    return a;
}
__device__ __forceinline__ void split8(const float* z, uint4& h, uint4& l) {
    uint32_t hw[4], lw[4];
#pragma unroll
    for (int q = 0; q < 4; ++q)
        split2(z[2 * q], z[2 * q + 1], hw[q], lw[q]);
    h = make_uint4(hw[0], hw[1], hw[2], hw[3]);
    l = make_uint4(lw[0], lw[1], lw[2], lw[3]);
}

#define LDSM4(r, addr) \
    asm volatile("ldmatrix.sync.aligned.m8n8.x4.shared.b16 {%0,%1,%2,%3}, [%4];" \
        : "=r"((r)[0]), "=r"((r)[1]), "=r"((r)[2]), "=r"((r)[3]) : "r"(addr))

#define MMA_BF16(c, a, b0, b1) \
    asm volatile("mma.sync.aligned.m16n8k16.row.col.f32.bf16.bf16.f32 " \
        "{%0,%1,%2,%3}, {%4,%5,%6,%7}, {%8,%9}, {%0,%1,%2,%3};" \
        : "+f"((c)[0]), "+f"((c)[1]), "+f"((c)[2]), "+f"((c)[3]) \
        : "r"((a)[0]), "r"((a)[1]), "r"((a)[2]), "r"((a)[3]), "r"(b0), "r"(b1))

__global__ __launch_bounds__(256, 1) void fused_pair_mlp_mma(
    const float* __restrict__ x,
    const void*  __restrict__ samples_raw,
    const float* __restrict__ b1,
    const float* __restrict__ W2,
    const float* __restrict__ b2,
    float* __restrict__ out,
    int S, int n_nodes)
{
    extern __shared__ __align__(16) char dsm[];     // A buffers (40960 B)
    __shared__ float  sb1[256];
    __shared__ float2 sw2[256];
    __shared__ float2 red[BM * 4];

    const uint32_t sb = smem_u32(dsm);
    const int tid  = threadIdx.x;
    const int lane = tid & 31;
    const int wid  = tid >> 5;
    const int mw   = wid >> 2;      // 0..1 (M 2x64)
    const int nw   = wid & 3;       // 0..3 (N 4x64)
    const int m0   = blockIdx.x * BM;

    sb1[tid] = b1[tid];
    sw2[tid] = *(const float2*)&W2[tid * 2];

    // ---- dtype detection: int64 vs int32 sample indices (uniform)
    const long long* s64 = (const long long*)samples_raw;
    const int*       s32 = (const int*)samples_raw;
    bool is64 = true;
#pragma unroll
    for (int i = 0; i < 4; ++i) {
        long long v = __ldg(&s64[i]);
        if (v < 0 || v >= (long long)n_nodes) is64 = false;
    }

    // ---- A staging map: thread t -> row t>>1 (0..127), 16 k's at (t&1)*16
    const int arow = tid >> 1;
    const int half = tid & 1;
    int gr = m0 + arow; if (gr >= S) gr = S - 1;
    long long ia, ib;
    if (is64) { ia = s64[(long long)gr * 2]; ib = s64[(long long)gr * 2 + 1]; }
    else      { ia = s32[gr * 2];            ib = s32[gr * 2 + 1]; }
    const float* xa = x + ia * KD + half * 16;
    const float* xb = x + ib * KD + half * 16;
    const uint32_t stsOff = (uint32_t)(arow * 80 + half * 32);

    // ---- ldmatrix A per-lane base (row-major 16x16 tiles, 80B row stride)
    const uint32_t aLane =
        2u * ((mw * 64 + (lane & 15)) * 40 + ((lane >> 4) << 3));

    float acc[4][8][4];
#pragma unroll
    for (int i = 0; i < 4; ++i)
#pragma unroll
        for (int j = 0; j < 8; ++j)
#pragma unroll
            for (int q = 0; q < 4; ++q) acc[i][j][q] = 0.f;

    // ---- prologue: stage chunk 0 into buffer 0
    {
        float z[16];
#pragma unroll
        for (int j = 0; j < 4; ++j) {
            const float4 va = *(const float4*)(xa + j * 4);
            const float4 vb = *(const float4*)(xb + j * 4);
            z[j*4+0]=va.x*vb.x; z[j*4+1]=va.y*vb.y;
            z[j*4+2]=va.z*vb.z; z[j*4+3]=va.w*vb.w;
        }
#pragma unroll
        for (int g = 0; g < 2; ++g) {
            uint4 h, l;
            split8(&z[g * 8], h, l);
            *(uint4*)(dsm + stsOff + g * 16)         = h;
            *(uint4*)(dsm + 10240 + stsOff + g * 16) = l;
        }
    }
    __syncthreads();

    // ---- K loop: 8 chunks of 32
#pragma unroll 1
    for (int c = 0; c < NCH; ++c) {
        const int buf = c & 1;
        const uint32_t aBase = sb + buf * ABUF + aLane;
        const bool more = (c + 1 < NCH);

        // issue next chunk's gather loads (latency hidden under MMAs)
        float4 va[4], vb[4];
        if (more) {
            const int k0n = (c + 1) * KC;
#pragma unroll
            for (int j = 0; j < 4; ++j) {
                va[j] = *(const float4*)(xa + k0n + j * 4);
                vb[j] = *(const float4*)(xb + k0n + j * 4);
            }
        }

#pragma unroll
        for (int kk = 0; kk < 2; ++kk) {
            uint32_t ah[4][4], al[4][4];
#pragma unroll
            for (int tm = 0; tm < 4; ++tm) {
                LDSM4(ah[tm], aBase + tm * 1280 + kk * 32);
                LDSM4(al[tm], aBase + 10240 + tm * 1280 + kk * 32);
            }
            const uint4* pB = g_Wf + (c * 2 + kk) * 1024 + nw * 256 + lane;
            uint4 wB[8];
#pragma unroll
            for (int tn = 0; tn < 8; ++tn) wB[tn] = pB[tn * 32];
#pragma unroll
            for (int tn = 0; tn < 8; ++tn) {
#pragma unroll
                for (int tm = 0; tm < 4; ++tm) {
                    MMA_BF16(acc[tm][tn], ah[tm], wB[tn].x, wB[tn].y);
                    MMA_BF16(acc[tm][tn], ah[tm], wB[tn].z, wB[tn].w);
                    MMA_BF16(acc[tm][tn], al[tm], wB[tn].x, wB[tn].y);
                }
            }
        }

        if (more) {
            float z[16];
#pragma unroll
            for (int j = 0; j < 4; ++j) {
                z[j*4+0]=va[j].x*vb[j].x; z[j*4+1]=va[j].y*vb[j].y;
                z[j*4+2]=va[j].z*vb[j].z; z[j*4+3]=va[j].w*vb[j].w;
            }
            char* db = dsm + (buf ^ 1) * ABUF;
#pragma unroll
            for (int g = 0; g < 2; ++g) {
                uint4 h, l;
                split8(&z[g * 8], h, l);
                *(uint4*)(db + stsOff + g * 16)         = h;
                *(uint4*)(db + 10240 + stsOff + g * 16) = l;
            }
            __syncthreads();
        }
    }

    // ---- epilogue: bias + relu + [256,2] GEMM, warp-reduce then smem combine
    const int lr = lane >> 2;
    const int lc = (lane & 3) * 2;
#pragma unroll
    for (int tm = 0; tm < 4; ++tm) {
#pragma unroll
        for (int hh = 0; hh < 2; ++hh) {
            const int row = mw * 64 + tm * 16 + lr + hh * 8;
            float o0 = 0.f, o1 = 0.f;
#pragma unroll
            for (int tn = 0; tn < 8; ++tn) {
                const int cb = nw * 64 + tn * 8 + lc;
                const float z0 = fmaxf(acc[tm][tn][hh * 2 + 0] + sb1[cb], 0.f);
                const float z1 = fmaxf(acc[tm][tn][hh * 2 + 1] + sb1[cb + 1], 0.f);
                const float2 w0 = sw2[cb];
                const float2 w1 = sw2[cb + 1];
                o0 = fmaf(z0, w0.x, fmaf(z1, w1.x, o0));
                o1 = fmaf(z0, w0.y, fmaf(z1, w1.y, o1));
            }
            o0 += __shfl_xor_sync(0xffffffffu, o0, 1);
            o0 += __shfl_xor_sync(0xffffffffu, o0, 2);
            o1 += __shfl_xor_sync(0xffffffffu, o1, 1);
            o1 += __shfl_xor_sync(0xffffffffu, o1, 2);
            if ((lane & 3) == 0) red[row * 4 + nw] = make_float2(o0, o1);
        }
    }
    __syncthreads();

    if (tid < BM) {
        const int m = m0 + tid;
        if (m < S) {
            float2 s = red[tid * 4];
#pragma unroll
            for (int q = 1; q < 4; ++q) {
                s.x += red[tid * 4 + q].x;
                s.y += red[tid * 4 + q].y;
            }
            float2 o;
            o.x = s.x + b2[0];
            o.y = s.y + b2[1];
            *(float2*)(out + m * 2) = o;
        }
    }
}

extern "C" void kernel_launch(void* const* d_in, const int* in_sizes, int n_in,
                              void* d_out, int out_size) {
    // metadata order: x_feature, edge_index, samples, W1, b1, W2, b2,
    //                 lin1_W, lin1_b, lin2_W, lin2_b
    const float* x       = (const float*)d_in[0];
    const void*  samples = d_in[2];
    const float* lin1_W  = (const float*)d_in[7];
    const float* lin1_b  = (const float*)d_in[8];
    const float* lin2_W  = (const float*)d_in[9];
    const float* lin2_b  = (const float*)d_in[10];
    float* out = (float*)d_out;

    const int S       = in_sizes[2] / 2;
    const int n_nodes = in_sizes[0] / KD;
    const int grid    = (S + BM - 1) / BM;

    conv_w_kernel<<<64, 256>>>(lin1_W);

    cudaFuncSetAttribute(fused_pair_mlp_mma,
                         cudaFuncAttributeMaxDynamicSharedMemorySize, DSMEM);
    fused_pair_mlp_mma<<<grid, 256, DSMEM>>>(
        x, samples, lin1_b, lin2_W, lin2_b, out, S, n_nodes);
}

// round 7
// speedup vs baseline: 4.0697x; 1.0089x over previous
#include <cuda_runtime.h>
#include <cuda_bf16.h>
#include <stdint.h>

// Effective computation (GNN stack is dead code in the reference):
//   z   = x[samples[:,0]] * x[samples[:,1]]          [S, 256]
//   z   = relu(z @ lin1_W + lin1_b)                  [S, 256]
//   out = z @ lin2_W + lin2_b                        [S, 2]
//
// R6: mma.sync bf16 (m16n8k16) 2-term split (3 MMA terms), pre-packed B
// fragments. 512 threads / 16 warps (4m x 4n), warp tile 32x64,
// term-major MMA ordering (RAW reuse distance 8), double-buffered A smem.

#define KD  256
#define BM  128
#define KC  32
#define NCH 8

#define ABUF  20480              // per-buffer: AH 10240 + AL 10240
#define DSMEM (2 * ABUF)         // 40960

// W1 fragments: [c][kk][ntile][lane] -> uint4 {b0h, b1h, b0l, b1l}
__device__ uint4 g_Wf[NCH * 2 * 32 * 32];

__device__ __forceinline__ uint32_t pack_bf16x2(float lo, float hi) {
    uint32_t r;   // low 16 <- lo
    asm("cvt.rn.bf16x2.f32 %0, %1, %2;" : "=r"(r) : "f"(hi), "f"(lo));
    return r;
}
__device__ __forceinline__ void split2(float a, float b, uint32_t& h, uint32_t& l) {
    h = pack_bf16x2(a, b);
    const float ha = __uint_as_float(h << 16);
    const float hb = __uint_as_float(h & 0xffff0000u);
    l = pack_bf16x2(a - ha, b - hb);
}

__global__ void conv_w_kernel(const float* __restrict__ W1) {
    const int idx  = blockIdx.x * 256 + threadIdx.x;   // 16384 total
    const int lane = idx & 31;
    const int tile = (idx >> 5) & 31;
    const int kk   = (idx >> 10) & 1;
    const int c    = idx >> 11;
    const int n  = tile * 8 + (lane >> 2);
    const int k0 = c * KC + kk * 16 + (lane & 3) * 2;
    const float w00 = W1[(size_t)k0 * KD + n];
    const float w01 = W1[(size_t)(k0 + 1) * KD + n];
    const float w10 = W1[(size_t)(k0 + 8) * KD + n];
    const float w11 = W1[(size_t)(k0 + 9) * KD + n];
    uint32_t h0, l0, h1, l1;
    split2(w00, w01, h0, l0);
    split2(w10, w11, h1, l1);
    g_Wf[idx] = make_uint4(h0, h1, l0, l1);
}

__device__ __forceinline__ uint32_t smem_u32(const void* p) {
    uint32_t a;
    asm("{ .reg .u64 t; cvta.to.shared.u64 t, %1; cvt.u32.u64 %0, t; }"
        : "=r"(a) : "l"(p));
    return a;
}
__device__ __forceinline__ void split8(const float* z, uint4& h, uint4& l) {
    uint32_t hw[4], lw[4];
#pragma unroll
    for (int q = 0; q < 4; ++q)
        split2(z[2 * q], z[2 * q + 1], hw[q], lw[q]);
    h = make_uint4(hw[0], hw[1], hw[2], hw[3]);
    l = make_uint4(lw[0], lw[1], lw[2], lw[3]);
}

#define LDSM4(r, addr) \
    asm volatile("ldmatrix.sync.aligned.m8n8.x4.shared.b16 {%0,%1,%2,%3}, [%4];" \
        : "=r"((r)[0]), "=r"((r)[1]), "=r"((r)[2]), "=r"((r)[3]) : "r"(addr))

#define MMA_BF16(c, a, b0, b1) \
    asm volatile("mma.sync.aligned.m16n8k16.row.col.f32.bf16.bf16.f32 " \
        "{%0,%1,%2,%3}, {%4,%5,%6,%7}, {%8,%9}, {%0,%1,%2,%3};" \
        : "+f"((c)[0]), "+f"((c)[1]), "+f"((c)[2]), "+f"((c)[3]) \
        : "r"((a)[0]), "r"((a)[1]), "r"((a)[2]), "r"((a)[3]), "r"(b0), "r"(b1))

__global__ __launch_bounds__(512, 1) void fused_pair_mlp_mma(
    const float* __restrict__ x,
    const void*  __restrict__ samples_raw,
    const float* __restrict__ b1,
    const float* __restrict__ W2,
    const float* __restrict__ b2,
    float* __restrict__ out,
    int S, int n_nodes)
{
    extern __shared__ __align__(16) char dsm[];     // A buffers (40960 B)
    __shared__ float  sb1[256];
    __shared__ float2 sw2[256];
    __shared__ float2 red[BM * 4];

    const uint32_t sb = smem_u32(dsm);
    const int tid  = threadIdx.x;
    const int lane = tid & 31;
    const int wid  = tid >> 5;
    const int mw   = wid >> 2;      // 0..3 (M 4x32)
    const int nw   = wid & 3;       // 0..3 (N 4x64)
    const int m0   = blockIdx.x * BM;

    if (tid < 256) {
        sb1[tid] = b1[tid];
        sw2[tid] = *(const float2*)&W2[tid * 2];
    }

    // ---- dtype detection: int64 vs int32 sample indices (uniform)
    const long long* s64 = (const long long*)samples_raw;
    const int*       s32 = (const int*)samples_raw;
    bool is64 = true;
#pragma unroll
    for (int i = 0; i < 4; ++i) {
        long long v = __ldg(&s64[i]);
        if (v < 0 || v >= (long long)n_nodes) is64 = false;
    }

    // ---- A staging map: thread t -> row t>>2 (0..127), 8 k's at (t&3)*8
    const int arow = tid >> 2;
    const int q    = tid & 3;
    int gr = m0 + arow; if (gr >= S) gr = S - 1;
    long long ia, ib;
    if (is64) { ia = s64[(long long)gr * 2]; ib = s64[(long long)gr * 2 + 1]; }
    else      { ia = s32[gr * 2];            ib = s32[gr * 2 + 1]; }
    const float* xa = x + ia * KD + q * 8;
    const float* xb = x + ib * KD + q * 8;
    const uint32_t stsOff = (uint32_t)(arow * 80 + q * 16);

    // ---- ldmatrix A per-lane base (row-major m16 tiles, 80B row stride)
    const uint32_t aLane =
        2u * ((mw * 32 + (lane & 15)) * 40 + ((lane >> 4) << 3));

    float acc[2][8][4];
#pragma unroll
    for (int i = 0; i < 2; ++i)
#pragma unroll
        for (int j = 0; j < 8; ++j)
#pragma unroll
            for (int p = 0; p < 4; ++p) acc[i][j][p] = 0.f;

    // ---- prologue: stage chunk 0 into buffer 0
    {
        float z[8];
        const float4 va0 = *(const float4*)xa;
        const float4 va1 = *(const float4*)(xa + 4);
        const float4 vb0 = *(const float4*)xb;
        const float4 vb1 = *(const float4*)(xb + 4);
        z[0]=va0.x*vb0.x; z[1]=va0.y*vb0.y; z[2]=va0.z*vb0.z; z[3]=va0.w*vb0.w;
        z[4]=va1.x*vb1.x; z[5]=va1.y*vb1.y; z[6]=va1.z*vb1.z; z[7]=va1.w*vb1.w;
        uint4 h, l;
        split8(z, h, l);
        *(uint4*)(dsm + stsOff)         = h;
        *(uint4*)(dsm + 10240 + stsOff) = l;
    }
    __syncthreads();

    // ---- K loop: 8 chunks of 32
#pragma unroll 1
    for (int c = 0; c < NCH; ++c) {
        const int buf = c & 1;
        const uint32_t aBase = sb + buf * ABUF + aLane;
        const bool more = (c + 1 < NCH);

        // next chunk's gather loads (16 regs, latency hidden under MMAs)
        float4 va0, va1, vb0, vb1;
        if (more) {
            const int k0n = (c + 1) * KC;
            va0 = *(const float4*)(xa + k0n);
            va1 = *(const float4*)(xa + k0n + 4);
            vb0 = *(const float4*)(xb + k0n);
            vb1 = *(const float4*)(xb + k0n + 4);
        }

#pragma unroll
        for (int kk = 0; kk < 2; ++kk) {
            uint32_t ah[2][4], al[2][4];
#pragma unroll
            for (int tm = 0; tm < 2; ++tm) {
                LDSM4(ah[tm], aBase + tm * 1280 + kk * 32);
                LDSM4(al[tm], aBase + 10240 + tm * 1280 + kk * 32);
            }
            const uint4* pB = g_Wf + (c * 2 + kk) * 1024 + nw * 8 * 32 + lane;
#pragma unroll
            for (int h2 = 0; h2 < 2; ++h2) {
                uint4 wB[4];
#pragma unroll
                for (int j = 0; j < 4; ++j) wB[j] = pB[(h2 * 4 + j) * 32];
                // term-major: same-acc reuse distance = 8 MMAs
#pragma unroll
                for (int tn = 0; tn < 4; ++tn)
#pragma unroll
                    for (int tm = 0; tm < 2; ++tm)
                        MMA_BF16(acc[tm][h2*4+tn], ah[tm], wB[tn].x, wB[tn].y);
#pragma unroll
                for (int tn = 0; tn < 4; ++tn)
#pragma unroll
                    for (int tm = 0; tm < 2; ++tm)
                        MMA_BF16(acc[tm][h2*4+tn], ah[tm], wB[tn].z, wB[tn].w);
#pragma unroll
                for (int tn = 0; tn < 4; ++tn)
#pragma unroll
                    for (int tm = 0; tm < 2; ++tm)
                        MMA_BF16(acc[tm][h2*4+tn], al[tm], wB[tn].x, wB[tn].y);
            }
        }

        if (more) {
            float z[8];
            z[0]=va0.x*vb0.x; z[1]=va0.y*vb0.y; z[2]=va0.z*vb0.z; z[3]=va0.w*vb0.w;
            z[4]=va1.x*vb1.x; z[5]=va1.y*vb1.y; z[6]=va1.z*vb1.z; z[7]=va1.w*vb1.w;
            uint4 h, l;
            split8(z, h, l);
            char* db = dsm + (buf ^ 1) * ABUF;
            *(uint4*)(db + stsOff)         = h;
            *(uint4*)(db + 10240 + stsOff) = l;
            __syncthreads();
        }
    }

    // ---- epilogue: bias + relu + [256,2] GEMM, warp-reduce then smem combine
    const int lr = lane >> 2;
    const int lc = (lane & 3) * 2;
#pragma unroll
    for (int tm = 0; tm < 2; ++tm) {
#pragma unroll
        for (int hh = 0; hh < 2; ++hh) {
            const int row = mw * 32 + tm * 16 + lr + hh * 8;
            float o0 = 0.f, o1 = 0.f;
#pragma unroll
            for (int tn = 0; tn < 8; ++tn) {
                const int cb = nw * 64 + tn * 8 + lc;
                const float z0 = fmaxf(acc[tm][tn][hh * 2 + 0] + sb1[cb], 0.f);
                const float z1 = fmaxf(acc[tm][tn][hh * 2 + 1] + sb1[cb + 1], 0.f);
                const float2 w0 = sw2[cb];
                const float2 w1 = sw2[cb + 1];
                o0 = fmaf(z0, w0.x, fmaf(z1, w1.x, o0));
                o1 = fmaf(z0, w0.y, fmaf(z1, w1.y, o1));
            }
            o0 += __shfl_xor_sync(0xffffffffu, o0, 1);
            o0 += __shfl_xor_sync(0xffffffffu, o0, 2);
            o1 += __shfl_xor_sync(0xffffffffu, o1, 1);
            o1 += __shfl_xor_sync(0xffffffffu, o1, 2);
            if ((lane & 3) == 0) red[row * 4 + nw] = make_float2(o0, o1);
        }
    }
    __syncthreads();

    if (tid < BM) {
        const int m = m0 + tid;
        if (m < S) {
            float2 s = red[tid * 4];
#pragma unroll
            for (int p = 1; p < 4; ++p) {
                s.x += red[tid * 4 + p].x;
                s.y += red[tid * 4 + p].y;
            }
            float2 o;
            o.x = s.x + b2[0];
            o.y = s.y + b2[1];
            *(float2*)(out + m * 2) = o;
        }
    }
}

extern "C" void kernel_launch(void* const* d_in, const int* in_sizes, int n_in,
                              void* d_out, int out_size) {
    // metadata order: x_feature, edge_index, samples, W1, b1, W2, b2,
    //                 lin1_W, lin1_b, lin2_W, lin2_b
    const float* x       = (const float*)d_in[0];
    const void*  samples = d_in[2];
    const float* lin1_W  = (const float*)d_in[7];
    const float* lin1_b  = (const float*)d_in[8];
    const float* lin2_W  = (const float*)d_in[9];
    const float* lin2_b  = (const float*)d_in[10];
    float* out = (float*)d_out;

    const int S       = in_sizes[2] / 2;
    const int n_nodes = in_sizes[0] / KD;
    const int grid    = (S + BM - 1) / BM;

    conv_w_kernel<<<64, 256>>>(lin1_W);

    cudaFuncSetAttribute(fused_pair_mlp_mma,
                         cudaFuncAttributeMaxDynamicSharedMemorySize, DSMEM);
    fused_pair_mlp_mma<<<grid, 512, DSMEM>>>(
        x, samples, lin1_b, lin2_W, lin2_b, out, S, n_nodes);
}

// round 8
// speedup vs baseline: 7.7473x; 1.9037x over previous
#include <cuda_runtime.h>
#include <cuda_fp16.h>
#include <stdint.h>

// Effective computation (GNN stack is dead code in the reference):
//   z   = x[samples[:,0]] * x[samples[:,1]]          [S, 256]
//   z   = relu(z @ lin1_W + lin1_b)                  [S, 256]
//   out = z @ lin2_W + lin2_b                        [S, 2]
//
// R7: single-term fp16 mma.sync (m16n8k16, f32 accum). fp16 rounding of z and
// W gives ~4e-4 RMS rel error (threshold 1e-3; anchored by R4's measured
// 4.2e-6 vs 2^-17.5 theory for the bf16 3-term variant). 3x fewer MMAs.
// 512 threads / 16 warps (4m x 4n), warp tile 32x64, CTA 128x256,
// pre-packed B fragments (LDG direct), double-buffered A smem.

#define KD  256
#define BM  128
#define KC  32
#define NCH 8

#define ABUF  10240              // per-buffer A: 128 rows x 80B
#define DSMEM (2 * ABUF)         // 20480

// W1 fp16 fragments: [kk_global 16][ntile 32][lane 32] -> uint2 {b0, b1}
__device__ uint2 g_Wf[16 * 32 * 32];

__device__ __forceinline__ uint32_t pack_f16x2(float lo, float hi) {
    uint32_t r;   // low 16 <- lo
    asm("cvt.rn.f16x2.f32 %0, %1, %2;" : "=r"(r) : "f"(hi), "f"(lo));
    return r;
}

__global__ void conv_w_kernel(const float* __restrict__ W1) {
    const int idx  = blockIdx.x * 256 + threadIdx.x;   // 16384 total
    const int lane = idx & 31;
    const int tile = (idx >> 5) & 31;
    const int kkg  = idx >> 10;                        // 0..15
    const int n  = tile * 8 + (lane >> 2);
    const int k0 = kkg * 16 + (lane & 3) * 2;
    const float w00 = W1[(size_t)k0 * KD + n];
    const float w01 = W1[(size_t)(k0 + 1) * KD + n];
    const float w10 = W1[(size_t)(k0 + 8) * KD + n];
    const float w11 = W1[(size_t)(k0 + 9) * KD + n];
    g_Wf[idx] = make_uint2(pack_f16x2(w00, w01), pack_f16x2(w10, w11));
}

__device__ __forceinline__ uint32_t smem_u32(const void* p) {
    uint32_t a;
    asm("{ .reg .u64 t; cvta.to.shared.u64 t, %1; cvt.u32.u64 %0, t; }"
        : "=r"(a) : "l"(p));
    return a;
}

#define LDSM4(r, addr) \
    asm volatile("ldmatrix.sync.aligned.m8n8.x4.shared.b16 {%0,%1,%2,%3}, [%4];" \
        : "=r"((r)[0]), "=r"((r)[1]), "=r"((r)[2]), "=r"((r)[3]) : "r"(addr))

#define MMA_F16(c, a, b0, b1) \
    asm volatile("mma.sync.aligned.m16n8k16.row.col.f32.f16.f16.f32 " \
        "{%0,%1,%2,%3}, {%4,%5,%6,%7}, {%8,%9}, {%0,%1,%2,%3};" \
        : "+f"((c)[0]), "+f"((c)[1]), "+f"((c)[2]), "+f"((c)[3]) \
        : "r"((a)[0]), "r"((a)[1]), "r"((a)[2]), "r"((a)[3]), "r"(b0), "r"(b1))

__global__ __launch_bounds__(512, 1) void fused_pair_mlp_mma(
    const float* __restrict__ x,
    const void*  __restrict__ samples_raw,
    const float* __restrict__ b1,
    const float* __restrict__ W2,
    const float* __restrict__ b2,
    float* __restrict__ out,
    int S, int n_nodes)
{
    extern __shared__ __align__(16) char dsm[];     // A buffers (fp16)
    __shared__ float  sb1[256];
    __shared__ float2 sw2[256];
    __shared__ float2 red[BM * 4];

    const uint32_t sb = smem_u32(dsm);
    const int tid  = threadIdx.x;
    const int lane = tid & 31;
    const int wid  = tid >> 5;
    const int mw   = wid >> 2;      // 0..3 (M 4x32)
    const int nw   = wid & 3;       // 0..3 (N 4x64)
    const int m0   = blockIdx.x * BM;

    if (tid < 256) {
        sb1[tid] = b1[tid];
        sw2[tid] = *(const float2*)&W2[tid * 2];
    }

    // ---- dtype detection: int64 vs int32 sample indices (uniform)
    const long long* s64 = (const long long*)samples_raw;
    const int*       s32 = (const int*)samples_raw;
    bool is64 = true;
#pragma unroll
    for (int i = 0; i < 4; ++i) {
        long long v = __ldg(&s64[i]);
        if (v < 0 || v >= (long long)n_nodes) is64 = false;
    }

    // ---- A staging map: thread t -> row t>>2 (0..127), 8 k's at (t&3)*8
    const int arow = tid >> 2;
    const int q    = tid & 3;
    int gr = m0 + arow; if (gr >= S) gr = S - 1;
    long long ia, ib;
    if (is64) { ia = s64[(long long)gr * 2]; ib = s64[(long long)gr * 2 + 1]; }
    else      { ia = s32[gr * 2];            ib = s32[gr * 2 + 1]; }
    const float* xa = x + ia * KD + q * 8;
    const float* xb = x + ib * KD + q * 8;
    const uint32_t stsOff = (uint32_t)(arow * 80 + q * 16);  // 8 fp16 = 16B

    // ---- ldmatrix A per-lane base (row-major m16 tiles, 80B row stride)
    const uint32_t aLane =
        2u * ((mw * 32 + (lane & 15)) * 40 + ((lane >> 4) << 3));

    float acc[2][8][4];
#pragma unroll
    for (int i = 0; i < 2; ++i)
#pragma unroll
        for (int j = 0; j < 8; ++j)
#pragma unroll
            for (int p = 0; p < 4; ++p) acc[i][j][p] = 0.f;

    // ---- prologue: stage chunk 0 into buffer 0 (8 products -> 8 fp16 = 16B)
    {
        const float4 va0 = *(const float4*)xa;
        const float4 va1 = *(const float4*)(xa + 4);
        const float4 vb0 = *(const float4*)xb;
        const float4 vb1 = *(const float4*)(xb + 4);
        uint4 h;
        h.x = pack_f16x2(va0.x * vb0.x, va0.y * vb0.y);
        h.y = pack_f16x2(va0.z * vb0.z, va0.w * vb0.w);
        h.z = pack_f16x2(va1.x * vb1.x, va1.y * vb1.y);
        h.w = pack_f16x2(va1.z * vb1.z, va1.w * vb1.w);
        *(uint4*)(dsm + stsOff) = h;
    }
    __syncthreads();

    // ---- K loop: 8 chunks of 32
#pragma unroll 1
    for (int c = 0; c < NCH; ++c) {
        const int buf = c & 1;
        const uint32_t aBase = sb + buf * ABUF + aLane;
        const bool more = (c + 1 < NCH);

        // next chunk's gather loads (latency hidden under kk0 MMAs)
        float4 va0, va1, vb0, vb1;
        if (more) {
            const int k0n = (c + 1) * KC;
            va0 = *(const float4*)(xa + k0n);
            va1 = *(const float4*)(xa + k0n + 4);
            vb0 = *(const float4*)(xb + k0n);
            vb1 = *(const float4*)(xb + k0n + 4);
        }

        // ---- kk = 0
        {
            uint32_t a0[4], a1[4];
            LDSM4(a0, aBase);
            LDSM4(a1, aBase + 1280);
            const uint2* pB = g_Wf + (c * 2) * 1024 + nw * 256 + lane;
            uint2 wB[8];
#pragma unroll
            for (int tn = 0; tn < 8; ++tn) wB[tn] = pB[tn * 32];
#pragma unroll
            for (int tn = 0; tn < 8; ++tn) {
                MMA_F16(acc[0][tn], a0, wB[tn].x, wB[tn].y);
                MMA_F16(acc[1][tn], a1, wB[tn].x, wB[tn].y);
            }
        }

        // stage next chunk into the other buffer (overlaps kk0 MMA drain)
        if (more) {
            uint4 h;
            h.x = pack_f16x2(va0.x * vb0.x, va0.y * vb0.y);
            h.y = pack_f16x2(va0.z * vb0.z, va0.w * vb0.w);
            h.z = pack_f16x2(va1.x * vb1.x, va1.y * vb1.y);
            h.w = pack_f16x2(va1.z * vb1.z, va1.w * vb1.w);
            *(uint4*)(dsm + (buf ^ 1) * ABUF + stsOff) = h;
        }

        // ---- kk = 1
        {
            uint32_t a0[4], a1[4];
            LDSM4(a0, aBase + 32);
            LDSM4(a1, aBase + 1280 + 32);
            const uint2* pB = g_Wf + (c * 2 + 1) * 1024 + nw * 256 + lane;
            uint2 wB[8];
#pragma unroll
            for (int tn = 0; tn < 8; ++tn) wB[tn] = pB[tn * 32];
#pragma unroll
            for (int tn = 0; tn < 8; ++tn) {
                MMA_F16(acc[0][tn], a0, wB[tn].x, wB[tn].y);
                MMA_F16(acc[1][tn], a1, wB[tn].x, wB[tn].y);
            }
        }

        if (more) __syncthreads();
    }

    // ---- epilogue: bias + relu + [256,2] GEMM, warp-reduce then smem combine
    const int lr = lane >> 2;
    const int lc = (lane & 3) * 2;
#pragma unroll
    for (int tm = 0; tm < 2; ++tm) {
#pragma unroll
        for (int hh = 0; hh < 2; ++hh) {
            const int row = mw * 32 + tm * 16 + lr + hh * 8;
            float o0 = 0.f, o1 = 0.f;
#pragma unroll
            for (int tn = 0; tn < 8; ++tn) {
                const int cb = nw * 64 + tn * 8 + lc;
                const float z0 = fmaxf(acc[tm][tn][hh * 2 + 0] + sb1[cb], 0.f);
                const float z1 = fmaxf(acc[tm][tn][hh * 2 + 1] + sb1[cb + 1], 0.f);
                const float2 w0 = sw2[cb];
                const float2 w1 = sw2[cb + 1];
                o0 = fmaf(z0, w0.x, fmaf(z1, w1.x, o0));
                o1 = fmaf(z0, w0.y, fmaf(z1, w1.y, o1));
            }
            o0 += __shfl_xor_sync(0xffffffffu, o0, 1);
            o0 += __shfl_xor_sync(0xffffffffu, o0, 2);
            o1 += __shfl_xor_sync(0xffffffffu, o1, 1);
            o1 += __shfl_xor_sync(0xffffffffu, o1, 2);
            if ((lane & 3) == 0) red[row * 4 + nw] = make_float2(o0, o1);
        }
    }
    __syncthreads();

    if (tid < BM) {
        const int m = m0 + tid;
        if (m < S) {
            float2 s = red[tid * 4];
#pragma unroll
            for (int p = 1; p < 4; ++p) {
                s.x += red[tid * 4 + p].x;
                s.y += red[tid * 4 + p].y;
            }
            float2 o;
            o.x = s.x + b2[0];
            o.y = s.y + b2[1];
            *(float2*)(out + m * 2) = o;
        }
    }
}

extern "C" void kernel_launch(void* const* d_in, const int* in_sizes, int n_in,
                              void* d_out, int out_size) {
    // metadata order: x_feature, edge_index, samples, W1, b1, W2, b2,
    //                 lin1_W, lin1_b, lin2_W, lin2_b
    const float* x       = (const float*)d_in[0];
    const void*  samples = d_in[2];
    const float* lin1_W  = (const float*)d_in[7];
    const float* lin1_b  = (const float*)d_in[8];
    const float* lin2_W  = (const float*)d_in[9];
    const float* lin2_b  = (const float*)d_in[10];
    float* out = (float*)d_out;

    const int S       = in_sizes[2] / 2;
    const int n_nodes = in_sizes[0] / KD;
    const int grid    = (S + BM - 1) / BM;

    conv_w_kernel<<<64, 256>>>(lin1_W);

    cudaFuncSetAttribute(fused_pair_mlp_mma,
                         cudaFuncAttributeMaxDynamicSharedMemorySize, DSMEM);
    fused_pair_mlp_mma<<<grid, 512, DSMEM>>>(
        x, samples, lin1_b, lin2_W, lin2_b, out, S, n_nodes);
}